// round 9
// baseline (speedup 1.0000x reference)
#include <cuda_runtime.h>
#include <cuda_fp16.h>

#define MAX_N 50000
#define MAX_E 600000
#define D 128
#define NB_MAX 1024   // max scan blocks supported

// scratch (no allocation allowed -> __device__ globals)
__device__ __half g_h1[MAX_N * D];
__device__ __half g_agg1h[MAX_N * D];   // relu(layer1 agg), fp16
__device__ __half g_h2[MAX_N * D];
__device__ float  g_deg[MAX_N];
__device__ float  g_dis[MAX_N];
__device__ int    g_cnt[MAX_N];
__device__ int    g_cnt2[MAX_N];
__device__ int    g_rowptr[MAX_N + 1];
__device__ int    g_bsum[NB_MAX];
__device__ int    g_boff[NB_MAX];
__device__ int2   g_edge[MAX_E];        // (src_row, norm bits) sorted by dst col
__device__ __half g_Wh1[D * D];         // fp16(W1)
__device__ __half g_Wr1[D * D];         // fp16(W1 - fp16(W1))  residual
__device__ __half g_Wh2[D * D];
__device__ __half g_Wr2[D * D];

// ---------------- init: zero deg/cnt/cnt2 ----------------
__global__ void init_kernel(int n) {
    int i = blockIdx.x * blockDim.x + threadIdx.x;
    if (i < n) {
        g_deg[i] = 0.f;
        g_cnt[i] = 0;
        g_cnt2[i] = 0;
    }
}

// ---------------- W split-convert: Wh = fp16(W), Wr = fp16(W - Wh) ----------------
__global__ void wconv_kernel(const float* __restrict__ W1, const float* __restrict__ W2) {
    int i = blockIdx.x * blockDim.x + threadIdx.x;
    if (i < D * D) {
        float w = W1[i];
        __half h = __float2half_rn(w);
        g_Wh1[i] = h;
        g_Wr1[i] = __float2half_rn(w - __half2float(h));
        w = W2[i];
        h = __float2half_rn(w);
        g_Wh2[i] = h;
        g_Wr2[i] = __float2half_rn(w - __half2float(h));
    }
}

// ---------------- CSR build ----------------
__global__ void hist_kernel(const float* __restrict__ w, const int* __restrict__ row,
                            const int* __restrict__ col, int E) {
    int e = blockIdx.x * blockDim.x + threadIdx.x;
    if (e < E) {
        atomicAdd(&g_deg[row[e]], w[e]);
        atomicAdd(&g_cnt[col[e]], 1);
    }
}

// pass 1: per-block sum of cnt, plus dis = rsqrt(deg) (parallel)
__global__ void bsum_kernel(int n) {
    __shared__ int ws[8];
    int i = blockIdx.x * 256 + threadIdx.x;
    int c = (i < n) ? g_cnt[i] : 0;
    if (i < n) g_dis[i] = rsqrtf(g_deg[i]);
    int v = c;
    #pragma unroll
    for (int o = 16; o > 0; o >>= 1) v += __shfl_down_sync(0xffffffff, v, o);
    if ((threadIdx.x & 31) == 0) ws[threadIdx.x >> 5] = v;
    __syncthreads();
    if (threadIdx.x < 8) {
        int s = ws[threadIdx.x];
        #pragma unroll
        for (int o = 4; o > 0; o >>= 1) s += __shfl_down_sync(0xff, s, o);
        if (threadIdx.x == 0) g_bsum[blockIdx.x] = s;
    }
}

// pass 2: exclusive scan of block sums (single small block)
__global__ void bscan_kernel(int nb) {
    __shared__ int sa[NB_MAX];
    __shared__ int sb[NB_MAX];
    int t = threadIdx.x;
    for (int i = t; i < NB_MAX; i += 1024) sa[i] = (i < nb) ? g_bsum[i] : 0;
    __syncthreads();
    int* src = sa;
    int* dst = sb;
    for (int off = 1; off < NB_MAX; off <<= 1) {
        for (int i = t; i < NB_MAX; i += 1024) {
            int v = src[i];
            if (i >= off) v += src[i - off];
            dst[i] = v;
        }
        __syncthreads();
        int* tmp = src; src = dst; dst = tmp;
    }
    for (int i = t; i < nb; i += 1024)
        g_boff[i] = (i == 0) ? 0 : src[i - 1];  // exclusive
}

// pass 3: block-local exclusive scan + block offset -> rowptr
__global__ void rowptr_kernel(int n, int E) {
    __shared__ int sa[256];
    __shared__ int sb[256];
    int t = threadIdx.x;
    int i = blockIdx.x * 256 + t;
    int c = (i < n) ? g_cnt[i] : 0;
    sa[t] = c;
    __syncthreads();
    int* src = sa;
    int* dst = sb;
    #pragma unroll
    for (int off = 1; off < 256; off <<= 1) {
        int v = src[t];
        if (t >= off) v += src[t - off];
        dst[t] = v;
        __syncthreads();
        int* tmp = src; src = dst; dst = tmp;
    }
    if (i < n) g_rowptr[i] = g_boff[blockIdx.x] + src[t] - c;  // exclusive
    if (blockIdx.x == 0 && t == 0) g_rowptr[n] = E;
}

__global__ void fill_kernel(const float* __restrict__ w, const int* __restrict__ row,
                            const int* __restrict__ col, int E) {
    int e = blockIdx.x * blockDim.x + threadIdx.x;
    if (e < E) {
        int c = col[e];
        int r = row[e];
        int pos = atomicAdd(&g_cnt2[c], 1);
        float nm = g_dis[r] * w[e] * g_dis[c];
        g_edge[g_rowptr[c] + pos] = make_int2(r, __float_as_int(nm));
    }
}

// ---------------- tensor-core GEMM: out_h = fp16(X @ W^T + b) ----------------
// mma.sync.m16n8k16, fp16 inputs, fp32 accum. W split into Wh + Wr for precision.
// Block = 256 threads (8 warps), tile = 128 rows x 128 cols, K=128 in 8 steps.
// Fragments loaded straight from global (L1-resident W), no smem/ldmatrix.
__device__ __forceinline__ void mma16816(float c[4], unsigned a0, unsigned a1,
                                         unsigned a2, unsigned a3,
                                         unsigned b0, unsigned b1) {
    asm("mma.sync.aligned.m16n8k16.row.col.f32.f16.f16.f32 "
        "{%0,%1,%2,%3},{%4,%5,%6,%7},{%8,%9},{%0,%1,%2,%3};"
        : "+f"(c[0]), "+f"(c[1]), "+f"(c[2]), "+f"(c[3])
        : "r"(a0), "r"(a1), "r"(a2), "r"(a3), "r"(b0), "r"(b1));
}

__device__ __forceinline__ unsigned h2u(__half2 h) { return *reinterpret_cast<unsigned*>(&h); }

template <bool A_FP32>
__global__ __launch_bounds__(256) void mma_gemm_kernel(const void* __restrict__ A_,
                                                       const __half* __restrict__ Wh,
                                                       const __half* __restrict__ Wr,
                                                       const float* __restrict__ bias,
                                                       __half* __restrict__ out, int n) {
    int warp = threadIdx.x >> 5;
    int lane = threadIdx.x & 31;
    int g = lane >> 2;    // groupID 0..7
    int tg = lane & 3;    // threadID_in_group
    int r0 = blockIdx.x * 128 + warp * 16;
    int rowA = r0 + g;        // C/A rows groupID
    int rowB = r0 + g + 8;    // rows groupID+8
    bool vA = rowA < n, vB = rowB < n;

    const float* Af = (const float*)A_;
    const __half* Ah = (const __half*)A_;

    float c[16][4];
    #pragma unroll
    for (int j = 0; j < 16; j++)
        #pragma unroll
        for (int q = 0; q < 4; q++) c[j][q] = 0.f;

    #pragma unroll
    for (int kk = 0; kk < 8; kk++) {
        int ka = kk * 16 + tg * 2;  // k column for this lane (low half); +8 for high
        unsigned a0, a1, a2, a3;
        if (A_FP32) {
            float2 f0 = vA ? *(const float2*)(Af + (size_t)rowA * D + ka) : make_float2(0.f, 0.f);
            float2 f1 = vB ? *(const float2*)(Af + (size_t)rowB * D + ka) : make_float2(0.f, 0.f);
            float2 f2 = vA ? *(const float2*)(Af + (size_t)rowA * D + ka + 8) : make_float2(0.f, 0.f);
            float2 f3 = vB ? *(const float2*)(Af + (size_t)rowB * D + ka + 8) : make_float2(0.f, 0.f);
            a0 = h2u(__floats2half2_rn(f0.x, f0.y));
            a1 = h2u(__floats2half2_rn(f1.x, f1.y));
            a2 = h2u(__floats2half2_rn(f2.x, f2.y));
            a3 = h2u(__floats2half2_rn(f3.x, f3.y));
        } else {
            a0 = vA ? *(const unsigned*)(Ah + (size_t)rowA * D + ka) : 0u;
            a1 = vB ? *(const unsigned*)(Ah + (size_t)rowB * D + ka) : 0u;
            a2 = vA ? *(const unsigned*)(Ah + (size_t)rowA * D + ka + 8) : 0u;
            a3 = vB ? *(const unsigned*)(Ah + (size_t)rowB * D + ka + 8) : 0u;
        }
        #pragma unroll
        for (int j = 0; j < 16; j++) {
            // B fragment: col n = j*8 + g, k rows tg*2..+1 (b0) and +8 (b1); W row-major [n][k]
            size_t wb = (size_t)(j * 8 + g) * D + kk * 16 + tg * 2;
            unsigned bh0 = *(const unsigned*)(Wh + wb);
            unsigned bh1 = *(const unsigned*)(Wh + wb + 8);
            mma16816(c[j], a0, a1, a2, a3, bh0, bh1);
            unsigned br0 = *(const unsigned*)(Wr + wb);
            unsigned br1 = *(const unsigned*)(Wr + wb + 8);
            mma16816(c[j], a0, a1, a2, a3, br0, br1);
        }
    }

    // epilogue: C rows rowA/rowB, cols j*8 + tg*2 (+1)
    #pragma unroll
    for (int j = 0; j < 16; j++) {
        int cc = j * 8 + tg * 2;
        float2 bv = *(const float2*)(bias + cc);
        if (vA) {
            __half2 o = __floats2half2_rn(c[j][0] + bv.x, c[j][1] + bv.y);
            *(__half2*)(out + (size_t)rowA * D + cc) = o;
        }
        if (vB) {
            __half2 o = __floats2half2_rn(c[j][2] + bv.x, c[j][3] + bv.y);
            *(__half2*)(out + (size_t)rowB * D + cc) = o;
        }
    }
}

// ---------------- gather: out[c] = sum_{e in CSR[c]} norm[e] * h[row[e]] ----------------
// h is fp16 (256B/row); warp per node; lane covers cols 4*lane..4*lane+3; unroll 4.
// HALF_RELU_OUT: store fp16 with relu (feeds layer-2 GEMM); else fp32.
__device__ __forceinline__ void gacc(float4& a, float nm, uint2 u) {
    float2 f0 = __half22float2(*(__half2*)&u.x);
    float2 f1 = __half22float2(*(__half2*)&u.y);
    a.x += nm * f0.x; a.y += nm * f0.y; a.z += nm * f1.x; a.w += nm * f1.y;
}

template <bool HALF_RELU_OUT>
__global__ void gather_kernel(const uint2* __restrict__ h, void* __restrict__ out_, int n) {
    int warp = (blockIdx.x * blockDim.x + threadIdx.x) >> 5;
    int lane = threadIdx.x & 31;
    if (warp >= n) return;
    int start = g_rowptr[warp];
    int end = g_rowptr[warp + 1];
    float4 a0 = make_float4(0.f, 0.f, 0.f, 0.f);
    float4 a1 = make_float4(0.f, 0.f, 0.f, 0.f);
    float4 a2 = make_float4(0.f, 0.f, 0.f, 0.f);
    float4 a3 = make_float4(0.f, 0.f, 0.f, 0.f);
    int j = start;
    for (; j + 4 <= end; j += 4) {
        int2 e0 = g_edge[j];
        int2 e1 = g_edge[j + 1];
        int2 e2 = g_edge[j + 2];
        int2 e3 = g_edge[j + 3];
        uint2 u0 = __ldg(&h[(size_t)e0.x * 32 + lane]);
        uint2 u1 = __ldg(&h[(size_t)e1.x * 32 + lane]);
        uint2 u2 = __ldg(&h[(size_t)e2.x * 32 + lane]);
        uint2 u3 = __ldg(&h[(size_t)e3.x * 32 + lane]);
        gacc(a0, __int_as_float(e0.y), u0);
        gacc(a1, __int_as_float(e1.y), u1);
        gacc(a2, __int_as_float(e2.y), u2);
        gacc(a3, __int_as_float(e3.y), u3);
    }
    for (; j < end; j++) {
        int2 e0 = g_edge[j];
        uint2 u0 = __ldg(&h[(size_t)e0.x * 32 + lane]);
        gacc(a0, __int_as_float(e0.y), u0);
    }
    float4 r = make_float4(a0.x + a1.x + a2.x + a3.x,
                           a0.y + a1.y + a2.y + a3.y,
                           a0.z + a1.z + a2.z + a3.z,
                           a0.w + a1.w + a2.w + a3.w);
    if (HALF_RELU_OUT) {
        __half2 p0 = __floats2half2_rn(fmaxf(r.x, 0.f), fmaxf(r.y, 0.f));
        __half2 p1 = __floats2half2_rn(fmaxf(r.z, 0.f), fmaxf(r.w, 0.f));
        uint2 u;
        u.x = *reinterpret_cast<unsigned*>(&p0);
        u.y = *reinterpret_cast<unsigned*>(&p1);
        *(uint2*)((__half*)out_ + (size_t)warp * D + lane * 4) = u;
    } else {
        *(float4*)((float*)out_ + (size_t)warp * D + lane * 4) = r;
    }
}

extern "C" void kernel_launch(void* const* d_in, const int* in_sizes, int n_in,
                              void* d_out, int out_size) {
    const float* x  = (const float*)d_in[0];
    const int*   ei = (const int*)d_in[1];
    const float* ew = (const float*)d_in[2];
    const float* W1 = (const float*)d_in[3];
    const float* b1 = (const float*)d_in[4];
    const float* W2 = (const float*)d_in[5];
    const float* b2 = (const float*)d_in[6];
    float* out = (float*)d_out;

    int n = in_sizes[0] / D;
    int E = in_sizes[2];
    const int* row = ei;
    const int* col = ei + E;

    void *p_h1, *p_agg1h, *p_h2, *p_Wh1, *p_Wr1, *p_Wh2, *p_Wr2;
    cudaGetSymbolAddress(&p_h1, g_h1);
    cudaGetSymbolAddress(&p_agg1h, g_agg1h);
    cudaGetSymbolAddress(&p_h2, g_h2);
    cudaGetSymbolAddress(&p_Wh1, g_Wh1);
    cudaGetSymbolAddress(&p_Wr1, g_Wr1);
    cudaGetSymbolAddress(&p_Wh2, g_Wh2);
    cudaGetSymbolAddress(&p_Wr2, g_Wr2);

    int nb = (n + 255) / 256;  // scan blocks (196 for n=50000, <= NB_MAX)

    // prep: init + W convert + CSR build (parallel scan)
    init_kernel<<<(n + 255) / 256, 256>>>(n);
    wconv_kernel<<<(D * D + 255) / 256, 256>>>(W1, W2);
    hist_kernel<<<(E + 255) / 256, 256>>>(ew, row, col, E);
    bsum_kernel<<<nb, 256>>>(n);
    bscan_kernel<<<1, 1024>>>(nb);
    rowptr_kernel<<<nb, 256>>>(n, E);
    fill_kernel<<<(E + 255) / 256, 256>>>(ew, row, col, E);

    int gemm_blocks = (n + 127) / 128;
    int gather_blocks = (n * 32 + 255) / 256;

    // layer 1 (tensor GEMM fp32 in -> fp16 h1, gather -> relu fp16 agg1h)
    mma_gemm_kernel<true><<<gemm_blocks, 256>>>(x, (const __half*)p_Wh1, (const __half*)p_Wr1,
                                                b1, (__half*)p_h1, n);
    gather_kernel<true><<<gather_blocks, 256>>>((const uint2*)p_h1, p_agg1h, n);

    // layer 2 (tensor GEMM fp16 in -> fp16 h2, gather -> fp32 out)
    mma_gemm_kernel<false><<<gemm_blocks, 256>>>(p_agg1h, (const __half*)p_Wh2, (const __half*)p_Wr2,
                                                 b2, (__half*)p_h2, n);
    gather_kernel<false><<<gather_blocks, 256>>>((const uint2*)p_h2, out, n);
}

// round 10
// speedup vs baseline: 1.6582x; 1.6582x over previous
#include <cuda_runtime.h>
#include <cuda_fp16.h>

#define MAX_N 50000
#define MAX_E 600000
#define D 128
#define NB_MAX 1024   // max scan blocks supported

// scratch (no allocation allowed -> __device__ globals)
__device__ __half g_h1[MAX_N * D];
__device__ __half g_agg1h[MAX_N * D];   // relu(layer1 agg), fp16
__device__ __half g_h2[MAX_N * D];
__device__ float  g_deg[MAX_N];
__device__ float  g_dis[MAX_N];
__device__ int    g_cnt[MAX_N];
__device__ int    g_cnt2[MAX_N];
__device__ int    g_rowptr[MAX_N + 1];
__device__ int    g_bsum[NB_MAX];
__device__ int    g_boff[NB_MAX];
__device__ int2   g_edge[MAX_E];        // (src_row, norm bits) sorted by dst col
// W packed in mma-fragment order: index (kk*16 + j)*32 + lane, payload {bh0,bh1,br0,br1}
__device__ uint4  g_Wp1[8 * 16 * 32];   // 64 KB
__device__ uint4  g_Wp2[8 * 16 * 32];

// ---------------- init: zero deg/cnt/cnt2 ----------------
__global__ void init_kernel(int n) {
    int i = blockIdx.x * blockDim.x + threadIdx.x;
    if (i < n) {
        g_deg[i] = 0.f;
        g_cnt[i] = 0;
        g_cnt2[i] = 0;
    }
}

// ---------------- W fragment-pack: split Wh=fp16(W), Wr=fp16(W-Wh), mma layout ----------------
__device__ __forceinline__ unsigned packh2(float x, float y) {
    __half2 h = __floats2half2_rn(x, y);
    return *reinterpret_cast<unsigned*>(&h);
}
__device__ __forceinline__ unsigned packres2(float x, float y) {
    __half hx = __float2half_rn(x);
    __half hy = __float2half_rn(y);
    __half2 h = __floats2half2_rn(x - __half2float(hx), y - __half2float(hy));
    return *reinterpret_cast<unsigned*>(&h);
}

__global__ void wconv_kernel(const float* __restrict__ W1, const float* __restrict__ W2) {
    int i = blockIdx.x * blockDim.x + threadIdx.x;
    if (i >= 8 * 16 * 32) return;
    int lane = i & 31;
    int j = (i >> 5) & 15;
    int kk = i >> 9;
    int g = lane >> 2, tg = lane & 3;
    int wrow = j * 8 + g;
    int wcol = kk * 16 + tg * 2;
    const float* ws[2] = {W1, W2};
    uint4* wp[2] = {g_Wp1, g_Wp2};
    #pragma unroll
    for (int s = 0; s < 2; s++) {
        const float* W = ws[s];
        float w0 = W[wrow * D + wcol],     w1 = W[wrow * D + wcol + 1];
        float w8 = W[wrow * D + wcol + 8], w9 = W[wrow * D + wcol + 9];
        uint4 v;
        v.x = packh2(w0, w1);
        v.y = packh2(w8, w9);
        v.z = packres2(w0, w1);
        v.w = packres2(w8, w9);
        wp[s][i] = v;
    }
}

// ---------------- CSR build ----------------
__global__ void hist_kernel(const float* __restrict__ w, const int* __restrict__ row,
                            const int* __restrict__ col, int E) {
    int e = blockIdx.x * blockDim.x + threadIdx.x;
    if (e < E) {
        atomicAdd(&g_deg[row[e]], w[e]);
        atomicAdd(&g_cnt[col[e]], 1);
    }
}

// pass 1: per-block sum of cnt, plus dis = rsqrt(deg) (parallel)
__global__ void bsum_kernel(int n) {
    __shared__ int ws[8];
    int i = blockIdx.x * 256 + threadIdx.x;
    int c = (i < n) ? g_cnt[i] : 0;
    if (i < n) g_dis[i] = rsqrtf(g_deg[i]);
    int v = c;
    #pragma unroll
    for (int o = 16; o > 0; o >>= 1) v += __shfl_down_sync(0xffffffff, v, o);
    if ((threadIdx.x & 31) == 0) ws[threadIdx.x >> 5] = v;
    __syncthreads();
    if (threadIdx.x < 8) {
        int s = ws[threadIdx.x];
        #pragma unroll
        for (int o = 4; o > 0; o >>= 1) s += __shfl_down_sync(0xff, s, o);
        if (threadIdx.x == 0) g_bsum[blockIdx.x] = s;
    }
}

// pass 2: exclusive scan of block sums (single small block)
__global__ void bscan_kernel(int nb) {
    __shared__ int sa[NB_MAX];
    __shared__ int sb[NB_MAX];
    int t = threadIdx.x;
    for (int i = t; i < NB_MAX; i += 1024) sa[i] = (i < nb) ? g_bsum[i] : 0;
    __syncthreads();
    int* src = sa;
    int* dst = sb;
    for (int off = 1; off < NB_MAX; off <<= 1) {
        for (int i = t; i < NB_MAX; i += 1024) {
            int v = src[i];
            if (i >= off) v += src[i - off];
            dst[i] = v;
        }
        __syncthreads();
        int* tmp = src; src = dst; dst = tmp;
    }
    for (int i = t; i < nb; i += 1024)
        g_boff[i] = (i == 0) ? 0 : src[i - 1];  // exclusive
}

// pass 3: block-local exclusive scan + block offset -> rowptr
__global__ void rowptr_kernel(int n, int E) {
    __shared__ int sa[256];
    __shared__ int sb[256];
    int t = threadIdx.x;
    int i = blockIdx.x * 256 + t;
    int c = (i < n) ? g_cnt[i] : 0;
    sa[t] = c;
    __syncthreads();
    int* src = sa;
    int* dst = sb;
    #pragma unroll
    for (int off = 1; off < 256; off <<= 1) {
        int v = src[t];
        if (t >= off) v += src[t - off];
        dst[t] = v;
        __syncthreads();
        int* tmp = src; src = dst; dst = tmp;
    }
    if (i < n) g_rowptr[i] = g_boff[blockIdx.x] + src[t] - c;  // exclusive
    if (blockIdx.x == 0 && t == 0) g_rowptr[n] = E;
}

__global__ void fill_kernel(const float* __restrict__ w, const int* __restrict__ row,
                            const int* __restrict__ col, int E) {
    int e = blockIdx.x * blockDim.x + threadIdx.x;
    if (e < E) {
        int c = col[e];
        int r = row[e];
        int pos = atomicAdd(&g_cnt2[c], 1);
        float nm = g_dis[r] * w[e] * g_dis[c];
        g_edge[g_rowptr[c] + pos] = make_int2(r, __float_as_int(nm));
    }
}

// ---------------- tensor-core GEMM: out_h = fp16(X @ W^T + b) ----------------
// mma.sync.m16n8k16, fp16 in, fp32 accum, split-W (value + residual) for precision.
// Block = 256 threads (8 warps), tile 128 rows; each warp: 16 rows x all 128 cols.
// B fragments come from the packed table: one coalesced LDG.128 per (j,kk) per lane.
__device__ __forceinline__ void mma16816(float c[4], unsigned a0, unsigned a1,
                                         unsigned a2, unsigned a3,
                                         unsigned b0, unsigned b1) {
    asm("mma.sync.aligned.m16n8k16.row.col.f32.f16.f16.f32 "
        "{%0,%1,%2,%3},{%4,%5,%6,%7},{%8,%9},{%0,%1,%2,%3};"
        : "+f"(c[0]), "+f"(c[1]), "+f"(c[2]), "+f"(c[3])
        : "r"(a0), "r"(a1), "r"(a2), "r"(a3), "r"(b0), "r"(b1));
}

__device__ __forceinline__ unsigned h2u(__half2 h) { return *reinterpret_cast<unsigned*>(&h); }

template <bool A_FP32>
__global__ __launch_bounds__(256) void mma_gemm_kernel(const void* __restrict__ A_,
                                                       const uint4* __restrict__ Wp,
                                                       const float* __restrict__ bias,
                                                       __half* __restrict__ out, int n) {
    int warp = threadIdx.x >> 5;
    int lane = threadIdx.x & 31;
    int g = lane >> 2;    // groupID 0..7
    int tg = lane & 3;    // threadID_in_group
    int r0 = blockIdx.x * 128 + warp * 16;
    int rowA = r0 + g;
    int rowB = r0 + g + 8;
    bool vA = rowA < n, vB = rowB < n;

    const float* Af = (const float*)A_;
    const __half* Ah = (const __half*)A_;

    // hoist all A fragments (K=128 -> 8 steps x 4 words)
    unsigned a[8][4];
    #pragma unroll
    for (int kk = 0; kk < 8; kk++) {
        int ka = kk * 16 + tg * 2;
        if (A_FP32) {
            float2 f0 = vA ? *(const float2*)(Af + (size_t)rowA * D + ka) : make_float2(0.f, 0.f);
            float2 f1 = vB ? *(const float2*)(Af + (size_t)rowB * D + ka) : make_float2(0.f, 0.f);
            float2 f2 = vA ? *(const float2*)(Af + (size_t)rowA * D + ka + 8) : make_float2(0.f, 0.f);
            float2 f3 = vB ? *(const float2*)(Af + (size_t)rowB * D + ka + 8) : make_float2(0.f, 0.f);
            a[kk][0] = h2u(__floats2half2_rn(f0.x, f0.y));
            a[kk][1] = h2u(__floats2half2_rn(f1.x, f1.y));
            a[kk][2] = h2u(__floats2half2_rn(f2.x, f2.y));
            a[kk][3] = h2u(__floats2half2_rn(f3.x, f3.y));
        } else {
            a[kk][0] = vA ? *(const unsigned*)(Ah + (size_t)rowA * D + ka) : 0u;
            a[kk][1] = vB ? *(const unsigned*)(Ah + (size_t)rowB * D + ka) : 0u;
            a[kk][2] = vA ? *(const unsigned*)(Ah + (size_t)rowA * D + ka + 8) : 0u;
            a[kk][3] = vB ? *(const unsigned*)(Ah + (size_t)rowB * D + ka + 8) : 0u;
        }
    }

    float c[16][4];
    #pragma unroll
    for (int j = 0; j < 16; j++)
        #pragma unroll
        for (int q = 0; q < 4; q++) c[j][q] = 0.f;

    #pragma unroll
    for (int kk = 0; kk < 8; kk++) {
        #pragma unroll
        for (int j = 0; j < 16; j++) {
            uint4 b = __ldg(&Wp[(kk * 16 + j) * 32 + lane]);  // coalesced 512B per warp
            mma16816(c[j], a[kk][0], a[kk][1], a[kk][2], a[kk][3], b.x, b.y);
            mma16816(c[j], a[kk][0], a[kk][1], a[kk][2], a[kk][3], b.z, b.w);
        }
    }

    // epilogue: C rows rowA/rowB, cols j*8 + tg*2 (+1)
    #pragma unroll
    for (int j = 0; j < 16; j++) {
        int cc = j * 8 + tg * 2;
        float2 bv = *(const float2*)(bias + cc);
        if (vA) {
            __half2 o = __floats2half2_rn(c[j][0] + bv.x, c[j][1] + bv.y);
            *(__half2*)(out + (size_t)rowA * D + cc) = o;
        }
        if (vB) {
            __half2 o = __floats2half2_rn(c[j][2] + bv.x, c[j][3] + bv.y);
            *(__half2*)(out + (size_t)rowB * D + cc) = o;
        }
    }
}

// ---------------- gather: out[c] = sum_{e in CSR[c]} norm[e] * h[row[e]] ----------------
// h is fp16 (256B/row); warp per node; lane covers cols 4*lane..4*lane+3; unroll 4.
// HALF_RELU_OUT: store fp16 with relu (feeds layer-2 GEMM); else fp32.
__device__ __forceinline__ void gacc(float4& a, float nm, uint2 u) {
    float2 f0 = __half22float2(*(__half2*)&u.x);
    float2 f1 = __half22float2(*(__half2*)&u.y);
    a.x += nm * f0.x; a.y += nm * f0.y; a.z += nm * f1.x; a.w += nm * f1.y;
}

template <bool HALF_RELU_OUT>
__global__ void gather_kernel(const uint2* __restrict__ h, void* __restrict__ out_, int n) {
    int warp = (blockIdx.x * blockDim.x + threadIdx.x) >> 5;
    int lane = threadIdx.x & 31;
    if (warp >= n) return;
    int start = g_rowptr[warp];
    int end = g_rowptr[warp + 1];
    float4 a0 = make_float4(0.f, 0.f, 0.f, 0.f);
    float4 a1 = make_float4(0.f, 0.f, 0.f, 0.f);
    float4 a2 = make_float4(0.f, 0.f, 0.f, 0.f);
    float4 a3 = make_float4(0.f, 0.f, 0.f, 0.f);
    int j = start;
    for (; j + 4 <= end; j += 4) {
        int2 e0 = g_edge[j];
        int2 e1 = g_edge[j + 1];
        int2 e2 = g_edge[j + 2];
        int2 e3 = g_edge[j + 3];
        uint2 u0 = __ldg(&h[(size_t)e0.x * 32 + lane]);
        uint2 u1 = __ldg(&h[(size_t)e1.x * 32 + lane]);
        uint2 u2 = __ldg(&h[(size_t)e2.x * 32 + lane]);
        uint2 u3 = __ldg(&h[(size_t)e3.x * 32 + lane]);
        gacc(a0, __int_as_float(e0.y), u0);
        gacc(a1, __int_as_float(e1.y), u1);
        gacc(a2, __int_as_float(e2.y), u2);
        gacc(a3, __int_as_float(e3.y), u3);
    }
    for (; j < end; j++) {
        int2 e0 = g_edge[j];
        uint2 u0 = __ldg(&h[(size_t)e0.x * 32 + lane]);
        gacc(a0, __int_as_float(e0.y), u0);
    }
    float4 r = make_float4(a0.x + a1.x + a2.x + a3.x,
                           a0.y + a1.y + a2.y + a3.y,
                           a0.z + a1.z + a2.z + a3.z,
                           a0.w + a1.w + a2.w + a3.w);
    if (HALF_RELU_OUT) {
        __half2 p0 = __floats2half2_rn(fmaxf(r.x, 0.f), fmaxf(r.y, 0.f));
        __half2 p1 = __floats2half2_rn(fmaxf(r.z, 0.f), fmaxf(r.w, 0.f));
        uint2 u;
        u.x = *reinterpret_cast<unsigned*>(&p0);
        u.y = *reinterpret_cast<unsigned*>(&p1);
        *(uint2*)((__half*)out_ + (size_t)warp * D + lane * 4) = u;
    } else {
        *(float4*)((float*)out_ + (size_t)warp * D + lane * 4) = r;
    }
}

extern "C" void kernel_launch(void* const* d_in, const int* in_sizes, int n_in,
                              void* d_out, int out_size) {
    const float* x  = (const float*)d_in[0];
    const int*   ei = (const int*)d_in[1];
    const float* ew = (const float*)d_in[2];
    const float* W1 = (const float*)d_in[3];
    const float* b1 = (const float*)d_in[4];
    const float* W2 = (const float*)d_in[5];
    const float* b2 = (const float*)d_in[6];
    float* out = (float*)d_out;

    int n = in_sizes[0] / D;
    int E = in_sizes[2];
    const int* row = ei;
    const int* col = ei + E;

    void *p_h1, *p_agg1h, *p_h2, *p_Wp1, *p_Wp2;
    cudaGetSymbolAddress(&p_h1, g_h1);
    cudaGetSymbolAddress(&p_agg1h, g_agg1h);
    cudaGetSymbolAddress(&p_h2, g_h2);
    cudaGetSymbolAddress(&p_Wp1, g_Wp1);
    cudaGetSymbolAddress(&p_Wp2, g_Wp2);

    int nb = (n + 255) / 256;  // scan blocks (196 for n=50000, <= NB_MAX)

    // prep: init + W fragment-pack + CSR build (parallel scan)
    init_kernel<<<(n + 255) / 256, 256>>>(n);
    wconv_kernel<<<(8 * 16 * 32 + 255) / 256, 256>>>(W1, W2);
    hist_kernel<<<(E + 255) / 256, 256>>>(ew, row, col, E);
    bsum_kernel<<<nb, 256>>>(n);
    bscan_kernel<<<1, 1024>>>(nb);
    rowptr_kernel<<<nb, 256>>>(n, E);
    fill_kernel<<<(E + 255) / 256, 256>>>(ew, row, col, E);

    int gemm_blocks = (n + 127) / 128;
    int gather_blocks = (n * 32 + 255) / 256;

    // layer 1 (tensor GEMM fp32 in -> fp16 h1, gather -> relu fp16 agg1h)
    mma_gemm_kernel<true><<<gemm_blocks, 256>>>(x, (const uint4*)p_Wp1, b1, (__half*)p_h1, n);
    gather_kernel<true><<<gather_blocks, 256>>>((const uint2*)p_h1, p_agg1h, n);

    // layer 2 (tensor GEMM fp16 in -> fp16 h2, gather -> fp32 out)
    mma_gemm_kernel<false><<<gemm_blocks, 256>>>(p_agg1h, (const uint4*)p_Wp2, b2, (__half*)p_h2, n);
    gather_kernel<false><<<gather_blocks, 256>>>((const uint2*)p_h2, out, n);
}

// round 11
// speedup vs baseline: 1.7749x; 1.0704x over previous
#include <cuda_runtime.h>
#include <cuda_fp16.h>

#define MAX_N 50000
#define MAX_E 600000
#define D 128
#define NB_MAX 1024   // max scan blocks supported

// scratch (no allocation allowed -> __device__ globals)
__device__ __half g_h1[MAX_N * D];
__device__ __half g_agg1h[MAX_N * D];   // relu(layer1 agg), fp16
__device__ __half g_h2[MAX_N * D];
__device__ float  g_deg[MAX_N];
__device__ float  g_dis[MAX_N];
__device__ int    g_cnt[MAX_N];
__device__ int    g_cnt2[MAX_N];
__device__ int    g_rowptr[MAX_N + 1];
__device__ int    g_bsum[NB_MAX];
__device__ int    g_boff[NB_MAX];
__device__ int2   g_edge[MAX_E];        // (src_row, norm bits) sorted by dst col
// W packed in mma-fragment order: index (kk*16 + j)*32 + lane, payload {bh0,bh1,br0,br1}
__device__ uint4  g_Wp1[8 * 16 * 32];   // 64 KB
__device__ uint4  g_Wp2[8 * 16 * 32];

// ---------------- fused init: zero deg/cnt/cnt2 + W fragment-pack ----------------
__device__ __forceinline__ unsigned packh2(float x, float y) {
    __half2 h = __floats2half2_rn(x, y);
    return *reinterpret_cast<unsigned*>(&h);
}
__device__ __forceinline__ unsigned packres2(float x, float y) {
    __half hx = __float2half_rn(x);
    __half hy = __float2half_rn(y);
    __half2 h = __floats2half2_rn(x - __half2float(hx), y - __half2float(hy));
    return *reinterpret_cast<unsigned*>(&h);
}

__global__ void prep_kernel(const float* __restrict__ W1, const float* __restrict__ W2, int n) {
    int i = blockIdx.x * blockDim.x + threadIdx.x;
    if (i < n) {
        g_deg[i] = 0.f;
        g_cnt[i] = 0;
        g_cnt2[i] = 0;
    }
    if (i < 8 * 16 * 32) {
        int lane = i & 31;
        int j = (i >> 5) & 15;
        int kk = i >> 9;
        int g = lane >> 2, tg = lane & 3;
        int wrow = j * 8 + g;
        int wcol = kk * 16 + tg * 2;
        const float* ws[2] = {W1, W2};
        uint4* wp[2] = {g_Wp1, g_Wp2};
        #pragma unroll
        for (int s = 0; s < 2; s++) {
            const float* W = ws[s];
            float w0 = W[wrow * D + wcol],     w1 = W[wrow * D + wcol + 1];
            float w8 = W[wrow * D + wcol + 8], w9 = W[wrow * D + wcol + 9];
            uint4 v;
            v.x = packh2(w0, w1);
            v.y = packh2(w8, w9);
            v.z = packres2(w0, w1);
            v.w = packres2(w8, w9);
            wp[s][i] = v;
        }
    }
}

// ---------------- CSR build ----------------
__global__ void hist_kernel(const float* __restrict__ w, const int* __restrict__ row,
                            const int* __restrict__ col, int E) {
    int e = blockIdx.x * blockDim.x + threadIdx.x;
    if (e < E) {
        atomicAdd(&g_deg[row[e]], w[e]);
        atomicAdd(&g_cnt[col[e]], 1);
    }
}

// pass 1: per-block sum of cnt, plus dis = rsqrt(deg) (parallel)
__global__ void bsum_kernel(int n) {
    __shared__ int ws[8];
    int i = blockIdx.x * 256 + threadIdx.x;
    int c = (i < n) ? g_cnt[i] : 0;
    if (i < n) g_dis[i] = rsqrtf(g_deg[i]);
    int v = c;
    #pragma unroll
    for (int o = 16; o > 0; o >>= 1) v += __shfl_down_sync(0xffffffff, v, o);
    if ((threadIdx.x & 31) == 0) ws[threadIdx.x >> 5] = v;
    __syncthreads();
    if (threadIdx.x < 8) {
        int s = ws[threadIdx.x];
        #pragma unroll
        for (int o = 4; o > 0; o >>= 1) s += __shfl_down_sync(0xff, s, o);
        if (threadIdx.x == 0) g_bsum[blockIdx.x] = s;
    }
}

// pass 2: exclusive scan of block sums (single small block)
__global__ void bscan_kernel(int nb) {
    __shared__ int sa[NB_MAX];
    __shared__ int sb[NB_MAX];
    int t = threadIdx.x;
    for (int i = t; i < NB_MAX; i += 1024) sa[i] = (i < nb) ? g_bsum[i] : 0;
    __syncthreads();
    int* src = sa;
    int* dst = sb;
    for (int off = 1; off < NB_MAX; off <<= 1) {
        for (int i = t; i < NB_MAX; i += 1024) {
            int v = src[i];
            if (i >= off) v += src[i - off];
            dst[i] = v;
        }
        __syncthreads();
        int* tmp = src; src = dst; dst = tmp;
    }
    for (int i = t; i < nb; i += 1024)
        g_boff[i] = (i == 0) ? 0 : src[i - 1];  // exclusive
}

// pass 3: block-local exclusive scan + block offset -> rowptr
__global__ void rowptr_kernel(int n, int E) {
    __shared__ int sa[256];
    __shared__ int sb[256];
    int t = threadIdx.x;
    int i = blockIdx.x * 256 + t;
    int c = (i < n) ? g_cnt[i] : 0;
    sa[t] = c;
    __syncthreads();
    int* src = sa;
    int* dst = sb;
    #pragma unroll
    for (int off = 1; off < 256; off <<= 1) {
        int v = src[t];
        if (t >= off) v += src[t - off];
        dst[t] = v;
        __syncthreads();
        int* tmp = src; src = dst; dst = tmp;
    }
    if (i < n) g_rowptr[i] = g_boff[blockIdx.x] + src[t] - c;  // exclusive
    if (blockIdx.x == 0 && t == 0) g_rowptr[n] = E;
}

__global__ void fill_kernel(const float* __restrict__ w, const int* __restrict__ row,
                            const int* __restrict__ col, int E) {
    int e = blockIdx.x * blockDim.x + threadIdx.x;
    if (e < E) {
        int c = col[e];
        int r = row[e];
        int pos = atomicAdd(&g_cnt2[c], 1);
        float nm = g_dis[r] * w[e] * g_dis[c];
        g_edge[g_rowptr[c] + pos] = make_int2(r, __float_as_int(nm));
    }
}

// ---------------- tensor-core GEMM: out_h = fp16(X @ W^T + b) ----------------
// mma.sync.m16n8k16, fp16 in, fp32 accum, split-W (value + residual) for precision.
// Block = 256 threads (8 warps), tile 128 rows; each warp: 16 rows x all 128 cols.
// B fragments come from the packed table: one coalesced LDG.128 per (j,kk) per lane.
__device__ __forceinline__ void mma16816(float c[4], unsigned a0, unsigned a1,
                                         unsigned a2, unsigned a3,
                                         unsigned b0, unsigned b1) {
    asm("mma.sync.aligned.m16n8k16.row.col.f32.f16.f16.f32 "
        "{%0,%1,%2,%3},{%4,%5,%6,%7},{%8,%9},{%0,%1,%2,%3};"
        : "+f"(c[0]), "+f"(c[1]), "+f"(c[2]), "+f"(c[3])
        : "r"(a0), "r"(a1), "r"(a2), "r"(a3), "r"(b0), "r"(b1));
}

__device__ __forceinline__ unsigned h2u(__half2 h) { return *reinterpret_cast<unsigned*>(&h); }

template <bool A_FP32>
__global__ __launch_bounds__(256) void mma_gemm_kernel(const void* __restrict__ A_,
                                                       const uint4* __restrict__ Wp,
                                                       const float* __restrict__ bias,
                                                       __half* __restrict__ out, int n) {
    int warp = threadIdx.x >> 5;
    int lane = threadIdx.x & 31;
    int g = lane >> 2;    // groupID 0..7
    int tg = lane & 3;    // threadID_in_group
    int r0 = blockIdx.x * 128 + warp * 16;
    int rowA = r0 + g;
    int rowB = r0 + g + 8;
    bool vA = rowA < n, vB = rowB < n;

    const float* Af = (const float*)A_;
    const __half* Ah = (const __half*)A_;

    // hoist all A fragments (K=128 -> 8 steps x 4 words)
    unsigned a[8][4];
    #pragma unroll
    for (int kk = 0; kk < 8; kk++) {
        int ka = kk * 16 + tg * 2;
        if (A_FP32) {
            float2 f0 = vA ? *(const float2*)(Af + (size_t)rowA * D + ka) : make_float2(0.f, 0.f);
            float2 f1 = vB ? *(const float2*)(Af + (size_t)rowB * D + ka) : make_float2(0.f, 0.f);
            float2 f2 = vA ? *(const float2*)(Af + (size_t)rowA * D + ka + 8) : make_float2(0.f, 0.f);
            float2 f3 = vB ? *(const float2*)(Af + (size_t)rowB * D + ka + 8) : make_float2(0.f, 0.f);
            a[kk][0] = h2u(__floats2half2_rn(f0.x, f0.y));
            a[kk][1] = h2u(__floats2half2_rn(f1.x, f1.y));
            a[kk][2] = h2u(__floats2half2_rn(f2.x, f2.y));
            a[kk][3] = h2u(__floats2half2_rn(f3.x, f3.y));
        } else {
            a[kk][0] = vA ? *(const unsigned*)(Ah + (size_t)rowA * D + ka) : 0u;
            a[kk][1] = vB ? *(const unsigned*)(Ah + (size_t)rowB * D + ka) : 0u;
            a[kk][2] = vA ? *(const unsigned*)(Ah + (size_t)rowA * D + ka + 8) : 0u;
            a[kk][3] = vB ? *(const unsigned*)(Ah + (size_t)rowB * D + ka + 8) : 0u;
        }
    }

    float c[16][4];
    #pragma unroll
    for (int j = 0; j < 16; j++)
        #pragma unroll
        for (int q = 0; q < 4; q++) c[j][q] = 0.f;

    #pragma unroll
    for (int kk = 0; kk < 8; kk++) {
        #pragma unroll
        for (int j = 0; j < 16; j++) {
            uint4 b = __ldg(&Wp[(kk * 16 + j) * 32 + lane]);  // coalesced 512B per warp
            mma16816(c[j], a[kk][0], a[kk][1], a[kk][2], a[kk][3], b.x, b.y);
            mma16816(c[j], a[kk][0], a[kk][1], a[kk][2], a[kk][3], b.z, b.w);
        }
    }

    // epilogue: C rows rowA/rowB, cols j*8 + tg*2 (+1)
    #pragma unroll
    for (int j = 0; j < 16; j++) {
        int cc = j * 8 + tg * 2;
        float2 bv = *(const float2*)(bias + cc);
        if (vA) {
            __half2 o = __floats2half2_rn(c[j][0] + bv.x, c[j][1] + bv.y);
            *(__half2*)(out + (size_t)rowA * D + cc) = o;
        }
        if (vB) {
            __half2 o = __floats2half2_rn(c[j][2] + bv.x, c[j][3] + bv.y);
            *(__half2*)(out + (size_t)rowB * D + cc) = o;
        }
    }
}

// ---------------- gather: out[c] = sum_{e in CSR[c]} norm[e] * h[row[e]] ----------------
// h fp16 (256B/row = 16 uint4). Warp per node; half-warps process alternate edges:
// lanes 0-15 edge j, lanes 16-31 edge j+1; each lane loads uint4 (8 cols).
// Cross-half shfl reduction at the end. Unroll 4 -> 8 edges in flight per warp.
__device__ __forceinline__ void gacc16(float acc[8], float nm, uint4 u) {
    float2 f0 = __half22float2(*(__half2*)&u.x);
    float2 f1 = __half22float2(*(__half2*)&u.y);
    float2 f2 = __half22float2(*(__half2*)&u.z);
    float2 f3 = __half22float2(*(__half2*)&u.w);
    acc[0] += nm * f0.x; acc[1] += nm * f0.y;
    acc[2] += nm * f1.x; acc[3] += nm * f1.y;
    acc[4] += nm * f2.x; acc[5] += nm * f2.y;
    acc[6] += nm * f3.x; acc[7] += nm * f3.y;
}

template <bool HALF_RELU_OUT>
__global__ void gather_kernel(const uint4* __restrict__ h, void* __restrict__ out_, int n) {
    int node = (blockIdx.x * blockDim.x + threadIdx.x) >> 5;
    int lane = threadIdx.x & 31;
    int lh = lane & 15;        // column chunk: cols lh*8 .. lh*8+7
    int half = lane >> 4;      // 0: even edges, 1: odd edges
    if (node >= n) return;
    int start = g_rowptr[node];
    int end = g_rowptr[node + 1];

    float acc[8] = {0.f, 0.f, 0.f, 0.f, 0.f, 0.f, 0.f, 0.f};

    int j = start + half;
    // unroll 4: this half handles j, j+2, j+4, j+6
    for (; j + 6 < end; j += 8) {
        int2 e0 = g_edge[j];
        int2 e1 = g_edge[j + 2];
        int2 e2 = g_edge[j + 4];
        int2 e3 = g_edge[j + 6];
        uint4 u0 = __ldg(&h[(size_t)e0.x * 16 + lh]);
        uint4 u1 = __ldg(&h[(size_t)e1.x * 16 + lh]);
        uint4 u2 = __ldg(&h[(size_t)e2.x * 16 + lh]);
        uint4 u3 = __ldg(&h[(size_t)e3.x * 16 + lh]);
        gacc16(acc, __int_as_float(e0.y), u0);
        gacc16(acc, __int_as_float(e1.y), u1);
        gacc16(acc, __int_as_float(e2.y), u2);
        gacc16(acc, __int_as_float(e3.y), u3);
    }
    for (; j < end; j += 2) {
        int2 e0 = g_edge[j];
        uint4 u0 = __ldg(&h[(size_t)e0.x * 16 + lh]);
        gacc16(acc, __int_as_float(e0.y), u0);
    }

    // combine halves
    #pragma unroll
    for (int q = 0; q < 8; q++)
        acc[q] += __shfl_xor_sync(0xffffffff, acc[q], 16);

    if (half == 0) {
        if (HALF_RELU_OUT) {
            __half2 p0 = __floats2half2_rn(fmaxf(acc[0], 0.f), fmaxf(acc[1], 0.f));
            __half2 p1 = __floats2half2_rn(fmaxf(acc[2], 0.f), fmaxf(acc[3], 0.f));
            __half2 p2 = __floats2half2_rn(fmaxf(acc[4], 0.f), fmaxf(acc[5], 0.f));
            __half2 p3 = __floats2half2_rn(fmaxf(acc[6], 0.f), fmaxf(acc[7], 0.f));
            uint4 u;
            u.x = *reinterpret_cast<unsigned*>(&p0);
            u.y = *reinterpret_cast<unsigned*>(&p1);
            u.z = *reinterpret_cast<unsigned*>(&p2);
            u.w = *reinterpret_cast<unsigned*>(&p3);
            *(uint4*)((__half*)out_ + (size_t)node * D + lh * 8) = u;
        } else {
            float* dst = (float*)out_ + (size_t)node * D + lh * 8;
            *(float4*)dst = make_float4(acc[0], acc[1], acc[2], acc[3]);
            *(float4*)(dst + 4) = make_float4(acc[4], acc[5], acc[6], acc[7]);
        }
    }
}

extern "C" void kernel_launch(void* const* d_in, const int* in_sizes, int n_in,
                              void* d_out, int out_size) {
    const float* x  = (const float*)d_in[0];
    const int*   ei = (const int*)d_in[1];
    const float* ew = (const float*)d_in[2];
    const float* W1 = (const float*)d_in[3];
    const float* b1 = (const float*)d_in[4];
    const float* W2 = (const float*)d_in[5];
    const float* b2 = (const float*)d_in[6];
    float* out = (float*)d_out;

    int n = in_sizes[0] / D;
    int E = in_sizes[2];
    const int* row = ei;
    const int* col = ei + E;

    void *p_h1, *p_agg1h, *p_h2, *p_Wp1, *p_Wp2;
    cudaGetSymbolAddress(&p_h1, g_h1);
    cudaGetSymbolAddress(&p_agg1h, g_agg1h);
    cudaGetSymbolAddress(&p_h2, g_h2);
    cudaGetSymbolAddress(&p_Wp1, g_Wp1);
    cudaGetSymbolAddress(&p_Wp2, g_Wp2);

    int nb = (n + 255) / 256;  // scan blocks (196 for n=50000, <= NB_MAX)

    // prep: fused init + W fragment-pack, then CSR build (parallel scan)
    prep_kernel<<<(n + 255) / 256, 256>>>(W1, W2, n);
    hist_kernel<<<(E + 255) / 256, 256>>>(ew, row, col, E);
    bsum_kernel<<<nb, 256>>>(n);
    bscan_kernel<<<1, 1024>>>(nb);
    rowptr_kernel<<<nb, 256>>>(n, E);
    fill_kernel<<<(E + 255) / 256, 256>>>(ew, row, col, E);

    int gemm_blocks = (n + 127) / 128;
    int gather_blocks = (n * 32 + 255) / 256;

    // layer 1 (tensor GEMM fp32 in -> fp16 h1, gather -> relu fp16 agg1h)
    mma_gemm_kernel<true><<<gemm_blocks, 256>>>(x, (const uint4*)p_Wp1, b1, (__half*)p_h1, n);
    gather_kernel<true><<<gather_blocks, 256>>>((const uint4*)p_h1, p_agg1h, n);

    // layer 2 (tensor GEMM fp16 in -> fp16 h2, gather -> fp32 out)
    mma_gemm_kernel<false><<<gemm_blocks, 256>>>(p_agg1h, (const uint4*)p_Wp2, b2, (__half*)p_h2, n);
    gather_kernel<false><<<gather_blocks, 256>>>((const uint4*)p_h2, out, n);
}

// round 13
// speedup vs baseline: 1.8797x; 1.0590x over previous
#include <cuda_runtime.h>
#include <cuda_fp16.h>

#define MAX_N 50000
#define MAX_E 600000
#define D 128

// scratch (no allocation allowed -> __device__ globals)
__device__ __half g_h1[MAX_N * D];
__device__ __half g_agg1h[MAX_N * D];   // relu(layer1 agg), fp16
__device__ __half g_h2[MAX_N * D];
__device__ float  g_deg[MAX_N];
__device__ float  g_dis[MAX_N];
__device__ int    g_cnt[MAX_N];
__device__ int    g_cnt2[MAX_N];
__device__ int    g_rowptr[MAX_N];      // start offset per node (chunk-ticket order)
__device__ int    g_total;              // ticket allocator
__device__ int2   g_edge[MAX_E];        // (src_row, norm bits) bucketed by dst col
// W packed in mma-fragment order: index (kk*16 + j)*32 + lane, payload {bh0,bh1,br0,br1}
__device__ uint4  g_Wp1[8 * 16 * 32];   // 64 KB
__device__ uint4  g_Wp2[8 * 16 * 32];

// ---------------- fused init: zero deg/cnt/cnt2/total + W fragment-pack ----------------
__device__ __forceinline__ unsigned packh2(float x, float y) {
    __half2 h = __floats2half2_rn(x, y);
    return *reinterpret_cast<unsigned*>(&h);
}
__device__ __forceinline__ unsigned packres2(float x, float y) {
    __half hx = __float2half_rn(x);
    __half hy = __float2half_rn(y);
    __half2 h = __floats2half2_rn(x - __half2float(hx), y - __half2float(hy));
    return *reinterpret_cast<unsigned*>(&h);
}

__global__ void prep_kernel(const float* __restrict__ W1, const float* __restrict__ W2, int n) {
    int i = blockIdx.x * blockDim.x + threadIdx.x;
    if (i == 0) g_total = 0;
    if (i < n) {
        g_deg[i] = 0.f;
        g_cnt[i] = 0;
        g_cnt2[i] = 0;
    }
    if (i < 8 * 16 * 32) {
        int lane = i & 31;
        int j = (i >> 5) & 15;
        int kk = i >> 9;
        int g = lane >> 2, tg = lane & 3;
        int wrow = j * 8 + g;
        int wcol = kk * 16 + tg * 2;
        const float* ws[2] = {W1, W2};
        uint4* wp[2] = {g_Wp1, g_Wp2};
        #pragma unroll
        for (int s = 0; s < 2; s++) {
            const float* W = ws[s];
            float w0 = W[wrow * D + wcol],     w1 = W[wrow * D + wcol + 1];
            float w8 = W[wrow * D + wcol + 8], w9 = W[wrow * D + wcol + 9];
            uint4 v;
            v.x = packh2(w0, w1);
            v.y = packh2(w8, w9);
            v.z = packres2(w0, w1);
            v.w = packres2(w8, w9);
            wp[s][i] = v;
        }
    }
}

// ---------------- CSR build ----------------
__global__ void hist_kernel(const float* __restrict__ w, const int* __restrict__ row,
                            const int* __restrict__ col, int E) {
    int e = blockIdx.x * blockDim.x + threadIdx.x;
    if (e < E) {
        atomicAdd(&g_deg[row[e]], w[e]);
        atomicAdd(&g_cnt[col[e]], 1);
    }
}

// single-pass: dis = rsqrt(deg); block-local scan of cnt; chunk base via atomic ticket.
// Chunk placement order across blocks is arbitrary — per-node buckets stay contiguous,
// and gather uses end = rowptr[i] + cnt[i], so no global ordering is required.
__global__ void scan2_kernel(int n) {
    __shared__ int sa[256];
    __shared__ int sb[256];
    __shared__ int sbase;
    int t = threadIdx.x;
    int i = blockIdx.x * 256 + t;
    int c = (i < n) ? g_cnt[i] : 0;
    if (i < n) g_dis[i] = rsqrtf(g_deg[i]);
    sa[t] = c;
    __syncthreads();
    int* src = sa;
    int* dst = sb;
    #pragma unroll
    for (int off = 1; off < 256; off <<= 1) {
        int v = src[t];
        if (t >= off) v += src[t - off];
        dst[t] = v;
        __syncthreads();
        int* tmp = src; src = dst; dst = tmp;
    }
    if (t == 255) sbase = atomicAdd(&g_total, src[255]);
    __syncthreads();
    if (i < n) g_rowptr[i] = sbase + src[t] - c;  // exclusive within chunk + chunk base
}

__global__ void fill_kernel(const float* __restrict__ w, const int* __restrict__ row,
                            const int* __restrict__ col, int E) {
    int e = blockIdx.x * blockDim.x + threadIdx.x;
    if (e < E) {
        int c = col[e];
        int r = row[e];
        int pos = atomicAdd(&g_cnt2[c], 1);
        float nm = g_dis[r] * w[e] * g_dis[c];
        g_edge[g_rowptr[c] + pos] = make_int2(r, __float_as_int(nm));
    }
}

// ---------------- tensor-core GEMM: out_h = fp16(X @ W^T + b) ----------------
// mma.sync.m16n8k16, fp16 in, fp32 accum, split-W (value + residual) for precision.
// Block = 256 threads (8 warps), tile 128 rows; each warp: 16 rows x all 128 cols.
// B fragments come from the packed table: one coalesced LDG.128 per (j,kk) per lane.
__device__ __forceinline__ void mma16816(float c[4], unsigned a0, unsigned a1,
                                         unsigned a2, unsigned a3,
                                         unsigned b0, unsigned b1) {
    asm("mma.sync.aligned.m16n8k16.row.col.f32.f16.f16.f32 "
        "{%0,%1,%2,%3},{%4,%5,%6,%7},{%8,%9},{%0,%1,%2,%3};"
        : "+f"(c[0]), "+f"(c[1]), "+f"(c[2]), "+f"(c[3])
        : "r"(a0), "r"(a1), "r"(a2), "r"(a3), "r"(b0), "r"(b1));
}

__device__ __forceinline__ unsigned h2u(__half2 h) { return *reinterpret_cast<unsigned*>(&h); }

template <bool A_FP32>
__global__ __launch_bounds__(256) void mma_gemm_kernel(const void* __restrict__ A_,
                                                       const uint4* __restrict__ Wp,
                                                       const float* __restrict__ bias,
                                                       __half* __restrict__ out, int n) {
    int warp = threadIdx.x >> 5;
    int lane = threadIdx.x & 31;
    int g = lane >> 2;    // groupID 0..7
    int tg = lane & 3;    // threadID_in_group
    int r0 = blockIdx.x * 128 + warp * 16;
    int rowA = r0 + g;
    int rowB = r0 + g + 8;
    bool vA = rowA < n, vB = rowB < n;

    const float* Af = (const float*)A_;
    const __half* Ah = (const __half*)A_;

    // hoist all A fragments (K=128 -> 8 steps x 4 words)
    unsigned a[8][4];
    #pragma unroll
    for (int kk = 0; kk < 8; kk++) {
        int ka = kk * 16 + tg * 2;
        if (A_FP32) {
            float2 f0 = vA ? *(const float2*)(Af + (size_t)rowA * D + ka) : make_float2(0.f, 0.f);
            float2 f1 = vB ? *(const float2*)(Af + (size_t)rowB * D + ka) : make_float2(0.f, 0.f);
            float2 f2 = vA ? *(const float2*)(Af + (size_t)rowA * D + ka + 8) : make_float2(0.f, 0.f);
            float2 f3 = vB ? *(const float2*)(Af + (size_t)rowB * D + ka + 8) : make_float2(0.f, 0.f);
            a[kk][0] = h2u(__floats2half2_rn(f0.x, f0.y));
            a[kk][1] = h2u(__floats2half2_rn(f1.x, f1.y));
            a[kk][2] = h2u(__floats2half2_rn(f2.x, f2.y));
            a[kk][3] = h2u(__floats2half2_rn(f3.x, f3.y));
        } else {
            a[kk][0] = vA ? *(const unsigned*)(Ah + (size_t)rowA * D + ka) : 0u;
            a[kk][1] = vB ? *(const unsigned*)(Ah + (size_t)rowB * D + ka) : 0u;
            a[kk][2] = vA ? *(const unsigned*)(Ah + (size_t)rowA * D + ka + 8) : 0u;
            a[kk][3] = vB ? *(const unsigned*)(Ah + (size_t)rowB * D + ka + 8) : 0u;
        }
    }

    float c[16][4];
    #pragma unroll
    for (int j = 0; j < 16; j++)
        #pragma unroll
        for (int q = 0; q < 4; q++) c[j][q] = 0.f;

    #pragma unroll
    for (int kk = 0; kk < 8; kk++) {
        #pragma unroll
        for (int j = 0; j < 16; j++) {
            uint4 b = __ldg(&Wp[(kk * 16 + j) * 32 + lane]);  // coalesced 512B per warp
            mma16816(c[j], a[kk][0], a[kk][1], a[kk][2], a[kk][3], b.x, b.y);
            mma16816(c[j], a[kk][0], a[kk][1], a[kk][2], a[kk][3], b.z, b.w);
        }
    }

    // epilogue: C rows rowA/rowB, cols j*8 + tg*2 (+1)
    #pragma unroll
    for (int j = 0; j < 16; j++) {
        int cc = j * 8 + tg * 2;
        float2 bv = *(const float2*)(bias + cc);
        if (vA) {
            __half2 o = __floats2half2_rn(c[j][0] + bv.x, c[j][1] + bv.y);
            *(__half2*)(out + (size_t)rowA * D + cc) = o;
        }
        if (vB) {
            __half2 o = __floats2half2_rn(c[j][2] + bv.x, c[j][3] + bv.y);
            *(__half2*)(out + (size_t)rowB * D + cc) = o;
        }
    }
}

// ---------------- gather: out[c] = sum_{e in bucket[c]} norm[e] * h[row[e]] ----------------
// h fp16 (256B/row = 16 uint4). Warp per node; half-warps process alternate edges:
// lanes 0-15 edge j, lanes 16-31 edge j+1; each lane loads uint4 (8 cols).
// Main loop unroll 4 (8 edges/warp), then dual (4 edges), then single tail.
__device__ __forceinline__ void gacc16(float acc[8], float nm, uint4 u) {
    float2 f0 = __half22float2(*(__half2*)&u.x);
    float2 f1 = __half22float2(*(__half2*)&u.y);
    float2 f2 = __half22float2(*(__half2*)&u.z);
    float2 f3 = __half22float2(*(__half2*)&u.w);
    acc[0] += nm * f0.x; acc[1] += nm * f0.y;
    acc[2] += nm * f1.x; acc[3] += nm * f1.y;
    acc[4] += nm * f2.x; acc[5] += nm * f2.y;
    acc[6] += nm * f3.x; acc[7] += nm * f3.y;
}

template <bool HALF_RELU_OUT>
__global__ void gather_kernel(const uint4* __restrict__ h, void* __restrict__ out_, int n) {
    int node = (blockIdx.x * blockDim.x + threadIdx.x) >> 5;
    int lane = threadIdx.x & 31;
    int lh = lane & 15;        // column chunk: cols lh*8 .. lh*8+7
    int half = lane >> 4;      // 0: even edges, 1: odd edges
    if (node >= n) return;
    int start = g_rowptr[node];
    int end = start + g_cnt[node];

    float acc[8] = {0.f, 0.f, 0.f, 0.f, 0.f, 0.f, 0.f, 0.f};

    int j = start + half;
    // unroll 4: this half handles j, j+2, j+4, j+6
    for (; j + 6 < end; j += 8) {
        int2 e0 = g_edge[j];
        int2 e1 = g_edge[j + 2];
        int2 e2 = g_edge[j + 4];
        int2 e3 = g_edge[j + 6];
        uint4 u0 = __ldg(&h[(size_t)e0.x * 16 + lh]);
        uint4 u1 = __ldg(&h[(size_t)e1.x * 16 + lh]);
        uint4 u2 = __ldg(&h[(size_t)e2.x * 16 + lh]);
        uint4 u3 = __ldg(&h[(size_t)e3.x * 16 + lh]);
        gacc16(acc, __int_as_float(e0.y), u0);
        gacc16(acc, __int_as_float(e1.y), u1);
        gacc16(acc, __int_as_float(e2.y), u2);
        gacc16(acc, __int_as_float(e3.y), u3);
    }
    // dual: j, j+2
    if (j + 2 < end) {
        int2 e0 = g_edge[j];
        int2 e1 = g_edge[j + 2];
        uint4 u0 = __ldg(&h[(size_t)e0.x * 16 + lh]);
        uint4 u1 = __ldg(&h[(size_t)e1.x * 16 + lh]);
        gacc16(acc, __int_as_float(e0.y), u0);
        gacc16(acc, __int_as_float(e1.y), u1);
        j += 4;
    }
    if (j < end) {
        int2 e0 = g_edge[j];
        uint4 u0 = __ldg(&h[(size_t)e0.x * 16 + lh]);
        gacc16(acc, __int_as_float(e0.y), u0);
    }

    // combine halves
    #pragma unroll
    for (int q = 0; q < 8; q++)
        acc[q] += __shfl_xor_sync(0xffffffff, acc[q], 16);

    if (half == 0) {
        if (HALF_RELU_OUT) {
            __half2 p0 = __floats2half2_rn(fmaxf(acc[0], 0.f), fmaxf(acc[1], 0.f));
            __half2 p1 = __floats2half2_rn(fmaxf(acc[2], 0.f), fmaxf(acc[3], 0.f));
            __half2 p2 = __floats2half2_rn(fmaxf(acc[4], 0.f), fmaxf(acc[5], 0.f));
            __half2 p3 = __floats2half2_rn(fmaxf(acc[6], 0.f), fmaxf(acc[7], 0.f));
            uint4 u;
            u.x = *reinterpret_cast<unsigned*>(&p0);
            u.y = *reinterpret_cast<unsigned*>(&p1);
            u.z = *reinterpret_cast<unsigned*>(&p2);
            u.w = *reinterpret_cast<unsigned*>(&p3);
            *(uint4*)((__half*)out_ + (size_t)node * D + lh * 8) = u;
        } else {
            float* dst = (float*)out_ + (size_t)node * D + lh * 8;
            *(float4*)dst = make_float4(acc[0], acc[1], acc[2], acc[3]);
            *(float4*)(dst + 4) = make_float4(acc[4], acc[5], acc[6], acc[7]);
        }
    }
}

extern "C" void kernel_launch(void* const* d_in, const int* in_sizes, int n_in,
                              void* d_out, int out_size) {
    const float* x  = (const float*)d_in[0];
    const int*   ei = (const int*)d_in[1];
    const float* ew = (const float*)d_in[2];
    const float* W1 = (const float*)d_in[3];
    const float* b1 = (const float*)d_in[4];
    const float* W2 = (const float*)d_in[5];
    const float* b2 = (const float*)d_in[6];
    float* out = (float*)d_out;

    int n = in_sizes[0] / D;
    int E = in_sizes[2];
    const int* row = ei;
    const int* col = ei + E;

    void *p_h1, *p_agg1h, *p_h2, *p_Wp1, *p_Wp2;
    cudaGetSymbolAddress(&p_h1, g_h1);
    cudaGetSymbolAddress(&p_agg1h, g_agg1h);
    cudaGetSymbolAddress(&p_h2, g_h2);
    cudaGetSymbolAddress(&p_Wp1, g_Wp1);
    cudaGetSymbolAddress(&p_Wp2, g_Wp2);

    int nb = (n + 255) / 256;

    // prep: fused init + W pack; hist; single-pass scan (atomic ticket); fill
    prep_kernel<<<nb, 256>>>(W1, W2, n);
    hist_kernel<<<(E + 255) / 256, 256>>>(ew, row, col, E);
    scan2_kernel<<<nb, 256>>>(n);
    fill_kernel<<<(E + 255) / 256, 256>>>(ew, row, col, E);

    int gemm_blocks = (n + 127) / 128;
    int gather_blocks = (n * 32 + 255) / 256;

    // layer 1 (tensor GEMM fp32 in -> fp16 h1, gather -> relu fp16 agg1h)
    mma_gemm_kernel<true><<<gemm_blocks, 256>>>(x, (const uint4*)p_Wp1, b1, (__half*)p_h1, n);
    gather_kernel<true><<<gather_blocks, 256>>>((const uint4*)p_h1, p_agg1h, n);

    // layer 2 (tensor GEMM fp16 in -> fp16 h2, gather -> fp32 out)
    mma_gemm_kernel<false><<<gemm_blocks, 256>>>(p_agg1h, (const uint4*)p_Wp2, b2, (__half*)p_h2, n);
    gather_kernel<false><<<gather_blocks, 256>>>((const uint4*)p_h2, out, n);
}